// round 6
// baseline (speedup 1.0000x reference)
#include <cuda_runtime.h>
#include <cuda_bf16.h>
#include <cstdint>
#include <cstddef>

#define LTOK 4096   // H*W tokens
#define CCH  512    // in channels
#define CIN  256    // inter channels
#define NBAT 4      // batch
#define EPSV 1e-5f

// ---------------- scratch (device globals: no runtime allocation) ----------
__device__ __nv_bfloat16 d_thh[(size_t)NBAT * LTOK * CIN];  // theta^T hi (L,CI)
__device__ __nv_bfloat16 d_thl[(size_t)NBAT * LTOK * CIN];  // theta^T lo
__device__ __nv_bfloat16 d_phh[(size_t)NBAT * LTOK * CIN];  // phi^T hi
__device__ __nv_bfloat16 d_phl[(size_t)NBAT * LTOK * CIN];  // phi^T lo
__device__ __nv_bfloat16 d_gh [(size_t)NBAT * CIN * LTOK];  // g hi (CI,L)
__device__ __nv_bfloat16 d_gl [(size_t)NBAT * CIN * LTOK];  // g lo
__device__ float         d_f  [(size_t)NBAT * LTOK * LTOK]; // 268 MB logits
__device__ __nv_bfloat16 d_ph_[(size_t)NBAT * LTOK * LTOK]; // softmax P hi
__device__ __nv_bfloat16 d_pl_[(size_t)NBAT * LTOK * LTOK]; // softmax P lo
__device__ __nv_bfloat16 d_y2h[(size_t)NBAT * LTOK * CIN];  // y2 hi (L,CI)
__device__ __nv_bfloat16 d_y2l[(size_t)NBAT * LTOK * CIN];  // y2 lo
__device__ __nv_bfloat16 d_wzh[CCH * CIN];
__device__ __nv_bfloat16 d_wzl[CCH * CIN];
__device__ float d_wy[(size_t)NBAT * CCH * LTOK];
__device__ float d_mean[CCH];
__device__ float d_rstd[CCH];

// =========================== helpers ========================================
__device__ __forceinline__ uint32_t smem_u32(const void* p) {
    uint32_t a;
    asm("{ .reg .u64 t; cvta.to.shared.u64 t, %1; cvt.u32.u64 %0, t; }" : "=r"(a) : "l"(p));
    return a;
}
__device__ __forceinline__ uint32_t cvt2bf(float x, float y) {
    uint32_t r;
    asm("cvt.rn.bf16x2.f32 %0, %1, %2;" : "=r"(r) : "f"(y), "f"(x));
    return r;
}
__device__ __forceinline__ void split2(float x, float y, uint32_t& h, uint32_t& l) {
    h = cvt2bf(x, y);
    const float hx = __uint_as_float(h << 16);
    const float hy = __uint_as_float(h & 0xffff0000u);
    l = cvt2bf(x - hx, y - hy);
}
__device__ __forceinline__ void mma16816(float c[4], const uint32_t a[4],
                                         uint32_t b0, uint32_t b1) {
    asm volatile(
        "mma.sync.aligned.m16n8k16.row.col.f32.bf16.bf16.f32 "
        "{%0,%1,%2,%3}, {%4,%5,%6,%7}, {%8,%9}, {%0,%1,%2,%3};"
        : "+f"(c[0]), "+f"(c[1]), "+f"(c[2]), "+f"(c[3])
        : "r"(a[0]), "r"(a[1]), "r"(a[2]), "r"(a[3]), "r"(b0), "r"(b1));
}
__device__ __forceinline__ void cp16(uint32_t dst, const void* src) {
    asm volatile("cp.async.cg.shared.global [%0], [%1], 16;" :: "r"(dst), "l"(src) : "memory");
}
#define CP_COMMIT() asm volatile("cp.async.commit_group;" ::: "memory")
#define CP_WAIT1()  asm volatile("cp.async.wait_group 1;" ::: "memory")

// =========== main GEMM: bf16 hi/lo pre-split inputs, cp.async pipeline ======
// D(MxN) = (Ah+Al)(MxK) · (Bh+Bl)(NxK)^T via 3 MMA terms. Row-major K-contig.
// CTA tile 128(M) x 256(N), K-step 64, 512 threads, 2 stages.
constexpr int SA_U = 128 * 36;                  // 4608 u32 per A matrix
constexpr int SB_U = 256 * 36;                  // 9216 u32 per B matrix
constexpr int STAGE_U = 2 * SA_U + 2 * SB_U;    // 27648 u32
constexpr int G_AH = 0, G_AL = SA_U, G_BH = 2 * SA_U, G_BL = 2 * SA_U + SB_U;
constexpr int GSMEM = 2 * STAGE_U * 4;          // 221184 B

template<int OUTM, bool BIAS>   // OUTM 0: fp32 D; 1: bf16 Dh/Dl
__global__ void __launch_bounds__(512, 1)
gemm_pre(const __nv_bfloat16* __restrict__ Ah, const __nv_bfloat16* __restrict__ Al,
         int lda, long long sA,
         const __nv_bfloat16* __restrict__ Bh, const __nv_bfloat16* __restrict__ Bl,
         int ldb, long long sB,
         float* __restrict__ D, __nv_bfloat16* __restrict__ Dh,
         __nv_bfloat16* __restrict__ Dl, int ldc, long long sD,
         const float* __restrict__ bias, int K)
{
    extern __shared__ uint32_t sm[];
    const uint32_t sbase = smem_u32(sm);
    Ah += (size_t)blockIdx.z * sA;  Al += (size_t)blockIdx.z * sA;
    Bh += (size_t)blockIdx.z * sB;  Bl += (size_t)blockIdx.z * sB;
    if (OUTM == 0) D += (size_t)blockIdx.z * sD;
    else { Dh += (size_t)blockIdx.z * sD; Dl += (size_t)blockIdx.z * sD; }

    const int bm = blockIdx.y * 128;
    const int bn = blockIdx.x * 256;
    const int tid  = threadIdx.x;
    const int lane = tid & 31;
    const int wid  = tid >> 5;
    const int wm = (wid & 3) * 32;    // 4 warps in M
    const int wn = (wid >> 2) * 64;   // 4 warps in N

    float acc[2][8][4];
#pragma unroll
    for (int a = 0; a < 2; a++)
#pragma unroll
        for (int b = 0; b < 8; b++)
#pragma unroll
            for (int c = 0; c < 4; c++) acc[a][b][c] = 0.f;

    const int KT = K / 64;

    auto issue = [&](int kt) {
        if (kt >= KT) return;
        const uint32_t sb = sbase + (uint32_t)(kt & 1) * (STAGE_U * 4);
        const int k0 = kt * 64;
#pragma unroll
        for (int p = 0; p < 2; p++) {
            const int c = tid + p * 512;
            const int r = c >> 3, cc = c & 7;
            const uint32_t d = sb + (uint32_t)((r * 36 + cc * 4) << 2);
            const size_t go = (size_t)(bm + r) * lda + k0 + cc * 8;
            cp16(d + G_AH * 4, Ah + go);
            cp16(d + G_AL * 4, Al + go);
        }
#pragma unroll
        for (int p = 0; p < 4; p++) {
            const int c = tid + p * 512;
            const int r = c >> 3, cc = c & 7;
            const uint32_t d = sb + (uint32_t)((r * 36 + cc * 4) << 2);
            const size_t go = (size_t)(bn + r) * ldb + k0 + cc * 8;
            cp16(d + G_BH * 4, Bh + go);
            cp16(d + G_BL * 4, Bl + go);
        }
    };

    issue(0); CP_COMMIT();
    issue(1); CP_COMMIT();

    const int arow = wm + (lane >> 2);
    const int brow = wn + (lane >> 2);
    const int kl = lane & 3;

    for (int kt = 0; kt < KT; kt++) {
        CP_WAIT1();
        __syncthreads();
        const uint32_t* s = sm + (kt & 1) * STAGE_U;
#pragma unroll
        for (int ss = 0; ss < 4; ss++) {
            const int kq = ss * 8 + kl;
            uint32_t Ahf[2][4], Alf[2][4];
#pragma unroll
            for (int mt = 0; mt < 2; mt++) {
                const int b0 = (arow + mt * 16) * 36 + kq;
                Ahf[mt][0] = s[G_AH + b0];       Ahf[mt][1] = s[G_AH + b0 + 288];
                Ahf[mt][2] = s[G_AH + b0 + 4];   Ahf[mt][3] = s[G_AH + b0 + 292];
                Alf[mt][0] = s[G_AL + b0];       Alf[mt][1] = s[G_AL + b0 + 288];
                Alf[mt][2] = s[G_AL + b0 + 4];   Alf[mt][3] = s[G_AL + b0 + 292];
            }
#pragma unroll
            for (int nt = 0; nt < 8; nt++) {
                const int c0 = (brow + nt * 8) * 36 + kq;
                const uint32_t b0h = s[G_BH + c0], b1h = s[G_BH + c0 + 4];
                const uint32_t b0l = s[G_BL + c0], b1l = s[G_BL + c0 + 4];
#pragma unroll
                for (int mt = 0; mt < 2; mt++) {
                    mma16816(acc[mt][nt], Ahf[mt], b0h, b1h);  // hi*hi
                    mma16816(acc[mt][nt], Ahf[mt], b0l, b1l);  // hi*lo
                    mma16816(acc[mt][nt], Alf[mt], b0h, b1h);  // lo*hi
                }
            }
        }
        __syncthreads();
        issue(kt + 2); CP_COMMIT();
    }

    // ---- epilogue ----
#pragma unroll
    for (int mt = 0; mt < 2; mt++) {
        const int r0 = bm + wm + mt * 16 + (lane >> 2);
        const float bv0 = BIAS ? bias[r0]     : 0.f;
        const float bv8 = BIAS ? bias[r0 + 8] : 0.f;
#pragma unroll
        for (int nt = 0; nt < 8; nt++) {
            const int c0 = bn + wn + nt * 8 + (lane & 3) * 2;
            if (OUTM == 0) {
                float2 v0, v1;
                v0.x = acc[mt][nt][0] + bv0; v0.y = acc[mt][nt][1] + bv0;
                v1.x = acc[mt][nt][2] + bv8; v1.y = acc[mt][nt][3] + bv8;
                *(float2*)&D[(size_t)r0 * ldc + c0]       = v0;
                *(float2*)&D[(size_t)(r0 + 8) * ldc + c0] = v1;
            } else {
                uint32_t h, l;
                split2(acc[mt][nt][0] + bv0, acc[mt][nt][1] + bv0, h, l);
                *(uint32_t*)(Dh + (size_t)r0 * ldc + c0) = h;
                *(uint32_t*)(Dl + (size_t)r0 * ldc + c0) = l;
                split2(acc[mt][nt][2] + bv8, acc[mt][nt][3] + bv8, h, l);
                *(uint32_t*)(Dh + (size_t)(r0 + 8) * ldc + c0) = h;
                *(uint32_t*)(Dl + (size_t)(r0 + 8) * ldc + c0) = l;
            }
        }
    }
}

// ===== bf16x3 split-precision GEMM from fp32 inputs (R3 variant, proj only) ==
// ADIR: A stored M x K (else K x M).  BDIR: B stored N x K (else K x N).
// BMODE: 0 none, 1 bias per M-row, 2 bias per N-col. Output: split bf16 Dh/Dl.
template<bool DIR>
__device__ __forceinline__ int sidx(int outer, int kp) {
    return DIR ? outer * 20 + kp : kp * 136 + outer;
}
constexpr int BUFU  = 10240;
constexpr int OFF_AH = 0, OFF_AL = 2560, OFF_BH = 5120, OFF_BL = 7680;
constexpr int PSMEM = 2 * BUFU * 4;   // 81920

template<bool ADIR, bool BDIR, int BMODE>
__global__ void __launch_bounds__(256, 1)
proj_bf16x3(const float* __restrict__ A, int lda, long long sA,
            const float* __restrict__ B, int ldb, long long sB,
            __nv_bfloat16* __restrict__ Dh, __nv_bfloat16* __restrict__ Dl,
            int ldc, long long sD,
            const float* __restrict__ bias, int K)
{
    extern __shared__ uint32_t sm[];
    A += (size_t)blockIdx.z * sA;
    B += (size_t)blockIdx.z * sB;
    Dh += (size_t)blockIdx.z * sD;
    Dl += (size_t)blockIdx.z * sD;

    const int bm = blockIdx.y * 128;
    const int bn = blockIdx.x * 128;
    const int tid  = threadIdx.x;
    const int lane = tid & 31;
    const int wm = ((tid >> 5) & 3) * 32;   // 4 warps in M
    const int wn = (tid >> 7) * 64;         // 2 warps in N

    float acc[2][8][4];
#pragma unroll
    for (int a = 0; a < 2; a++)
#pragma unroll
        for (int b = 0; b < 8; b++)
#pragma unroll
            for (int c = 0; c < 4; c++) acc[a][b][c] = 0.f;

    float4 ra[4], rb[4];

    auto ldgA = [&](int k0) {
        if (ADIR) {
#pragma unroll
            for (int p = 0; p < 4; p++) {
                const int i = tid + p * 256;
                ra[p] = *(const float4*)&A[(size_t)(bm + (i >> 3)) * lda + k0 + (i & 7) * 4];
            }
        } else {
#pragma unroll
            for (int p = 0; p < 2; p++) {
                const int j = tid + p * 256;
                const int kp = j >> 5, m4 = (j & 31) * 4;
                ra[2 * p]     = *(const float4*)&A[(size_t)(k0 + 2 * kp)     * lda + bm + m4];
                ra[2 * p + 1] = *(const float4*)&A[(size_t)(k0 + 2 * kp + 1) * lda + bm + m4];
            }
        }
    };
    auto ldgB = [&](int k0) {
        if (BDIR) {
#pragma unroll
            for (int p = 0; p < 4; p++) {
                const int i = tid + p * 256;
                rb[p] = *(const float4*)&B[(size_t)(bn + (i >> 3)) * ldb + k0 + (i & 7) * 4];
            }
        } else {
#pragma unroll
            for (int p = 0; p < 2; p++) {
                const int j = tid + p * 256;
                const int kp = j >> 5, m4 = (j & 31) * 4;
                rb[2 * p]     = *(const float4*)&B[(size_t)(k0 + 2 * kp)     * ldb + bn + m4];
                rb[2 * p + 1] = *(const float4*)&B[(size_t)(k0 + 2 * kp + 1) * ldb + bn + m4];
            }
        }
    };
    auto sts = [&](uint32_t* hi, uint32_t* lo, const float4* r, bool dir) {
        if (dir) {
#pragma unroll
            for (int p = 0; p < 4; p++) {
                const int i = tid + p * 256;
                const int rr = i >> 3, c2 = (i & 7) * 2;
                uint32_t h0, l0, h1, l1;
                split2(r[p].x, r[p].y, h0, l0);
                split2(r[p].z, r[p].w, h1, l1);
                hi[rr * 20 + c2] = h0; hi[rr * 20 + c2 + 1] = h1;
                lo[rr * 20 + c2] = l0; lo[rr * 20 + c2 + 1] = l1;
            }
        } else {
#pragma unroll
            for (int p = 0; p < 2; p++) {
                const int j = tid + p * 256;
                const int kp = j >> 5, m4 = (j & 31) * 4;
                const float* va = (const float*)&r[2 * p];
                const float* vb = (const float*)&r[2 * p + 1];
                uint4 H, L;
                split2(va[0], vb[0], H.x, L.x);
                split2(va[1], vb[1], H.y, L.y);
                split2(va[2], vb[2], H.z, L.z);
                split2(va[3], vb[3], H.w, L.w);
                *(uint4*)&hi[kp * 136 + m4] = H;
                *(uint4*)&lo[kp * 136 + m4] = L;
            }
        }
    };

    const int KT = K / 32;
    ldgA(0); ldgB(0);

    for (int kt = 0; kt < KT; kt++) {
        const int buf = kt & 1;
        uint32_t* base = sm + buf * BUFU;
        sts(base + OFF_AH, base + OFF_AL, ra, ADIR);
        sts(base + OFF_BH, base + OFF_BL, rb, BDIR);
        __syncthreads();
        if (kt + 1 < KT) { ldgA((kt + 1) * 32); ldgB((kt + 1) * 32); }

        const uint32_t* ah = sm + buf * BUFU + OFF_AH;
        const uint32_t* al = sm + buf * BUFU + OFF_AL;
        const uint32_t* bh = sm + buf * BUFU + OFF_BH;
        const uint32_t* bl = sm + buf * BUFU + OFF_BL;
#pragma unroll
        for (int s = 0; s < 2; s++) {
            const int kq = s * 8 + (lane & 3);
            uint32_t Ah[2][4], Al_[2][4];
#pragma unroll
            for (int mt = 0; mt < 2; mt++) {
                const int r = wm + mt * 16 + (lane >> 2);
                Ah[mt][0]  = ah[sidx<ADIR>(r,     kq)];
                Ah[mt][1]  = ah[sidx<ADIR>(r + 8, kq)];
                Ah[mt][2]  = ah[sidx<ADIR>(r,     kq + 4)];
                Ah[mt][3]  = ah[sidx<ADIR>(r + 8, kq + 4)];
                Al_[mt][0] = al[sidx<ADIR>(r,     kq)];
                Al_[mt][1] = al[sidx<ADIR>(r + 8, kq)];
                Al_[mt][2] = al[sidx<ADIR>(r,     kq + 4)];
                Al_[mt][3] = al[sidx<ADIR>(r + 8, kq + 4)];
            }
#pragma unroll
            for (int nt = 0; nt < 8; nt++) {
                const int n = wn + nt * 8 + (lane >> 2);
                const uint32_t b0h = bh[sidx<BDIR>(n, kq)];
                const uint32_t b1h = bh[sidx<BDIR>(n, kq + 4)];
                const uint32_t b0l = bl[sidx<BDIR>(n, kq)];
                const uint32_t b1l = bl[sidx<BDIR>(n, kq + 4)];
#pragma unroll
                for (int mt = 0; mt < 2; mt++) {
                    mma16816(acc[mt][nt], Ah[mt],  b0h, b1h);  // hi*hi
                    mma16816(acc[mt][nt], Ah[mt],  b0l, b1l);  // hi*lo
                    mma16816(acc[mt][nt], Al_[mt], b0h, b1h);  // lo*hi
                }
            }
        }
        __syncthreads();
    }

    // ---- epilogue: split bf16 output ----
#pragma unroll
    for (int mt = 0; mt < 2; mt++) {
        const int r0 = bm + wm + mt * 16 + (lane >> 2);
        const float bv0 = (BMODE == 1) ? bias[r0]     : 0.f;
        const float bv8 = (BMODE == 1) ? bias[r0 + 8] : 0.f;
#pragma unroll
        for (int nt = 0; nt < 8; nt++) {
            const int c0 = bn + wn + nt * 8 + (lane & 3) * 2;
            float cb0 = 0.f, cb1 = 0.f;
            if (BMODE == 2) { const float2 bb = *(const float2*)&bias[c0]; cb0 = bb.x; cb1 = bb.y; }
            uint32_t h, l;
            split2(acc[mt][nt][0] + bv0 + cb0, acc[mt][nt][1] + bv0 + cb1, h, l);
            *(uint32_t*)(Dh + (size_t)r0 * ldc + c0) = h;
            *(uint32_t*)(Dl + (size_t)r0 * ldc + c0) = l;
            split2(acc[mt][nt][2] + bv8 + cb0, acc[mt][nt][3] + bv8 + cb1, h, l);
            *(uint32_t*)(Dh + (size_t)(r0 + 8) * ldc + c0) = h;
            *(uint32_t*)(Dl + (size_t)(r0 + 8) * ldc + c0) = l;
        }
    }
}

// ---------------- Wz pre-split --------------------------------------------
__global__ __launch_bounds__(256)
void wz_split_kernel(const float* __restrict__ w,
                     __nv_bfloat16* __restrict__ wh, __nv_bfloat16* __restrict__ wl)
{
    const int p = blockIdx.x * 256 + threadIdx.x;   // pair index
    const float2 v = *(const float2*)&w[2 * p];
    uint32_t h, l;
    split2(v.x, v.y, h, l);
    ((uint32_t*)wh)[p] = h;
    ((uint32_t*)wl)[p] = l;
}

// ---------------- row softmax over f -> P hi/lo bf16 -------------------------
__global__ __launch_bounds__(256)
void softmax_kernel(const float* __restrict__ f,
                    __nv_bfloat16* __restrict__ ph, __nv_bfloat16* __restrict__ pl)
{
    const size_t rbase = (size_t)blockIdx.x * LTOK;
    const float* row = f + rbase;
    const int tid = threadIdx.x;

    float4 v[4];
    float m = -1e30f;
#pragma unroll
    for (int i = 0; i < 4; i++) {
        v[i] = *(const float4*)&row[tid * 4 + i * 1024];
        m = fmaxf(m, fmaxf(fmaxf(v[i].x, v[i].y), fmaxf(v[i].z, v[i].w)));
    }
#pragma unroll
    for (int o = 16; o; o >>= 1) m = fmaxf(m, __shfl_xor_sync(0xffffffffu, m, o));

    __shared__ float red[8];
    if ((tid & 31) == 0) red[tid >> 5] = m;
    __syncthreads();
    float gmax = -1e30f;
#pragma unroll
    for (int i = 0; i < 8; i++) gmax = fmaxf(gmax, red[i]);

    float s = 0.f;
#pragma unroll
    for (int i = 0; i < 4; i++) {
        v[i].x = __expf(v[i].x - gmax);
        v[i].y = __expf(v[i].y - gmax);
        v[i].z = __expf(v[i].z - gmax);
        v[i].w = __expf(v[i].w - gmax);
        s += v[i].x + v[i].y + v[i].z + v[i].w;
    }
#pragma unroll
    for (int o = 16; o; o >>= 1) s += __shfl_xor_sync(0xffffffffu, s, o);
    __syncthreads();
    if ((tid & 31) == 0) red[tid >> 5] = s;
    __syncthreads();
    float gsum = 0.f;
#pragma unroll
    for (int i = 0; i < 8; i++) gsum += red[i];
    const float inv = 1.f / gsum;

#pragma unroll
    for (int i = 0; i < 4; i++) {
        const float p0 = v[i].x * inv, p1 = v[i].y * inv;
        const float p2 = v[i].z * inv, p3 = v[i].w * inv;
        uint2 H, L;
        split2(p0, p1, H.x, L.x);
        split2(p2, p3, H.y, L.y);
        const size_t off = rbase + tid * 4 + i * 1024;
        *(uint2*)(ph + off) = H;
        *(uint2*)(pl + off) = L;
    }
}

// ---------------- batchnorm statistics ---------------------------------------
__global__ __launch_bounds__(256)
void bn_stats_kernel(const float* __restrict__ wy,
                     float* __restrict__ mean, float* __restrict__ rstd)
{
    const int c = blockIdx.x;
    float s = 0.f, s2 = 0.f;
    for (int idx = threadIdx.x; idx < NBAT * LTOK; idx += 256) {
        const int n = idx >> 12;
        const int l = idx & (LTOK - 1);
        const float v = wy[((size_t)n * CCH + c) * LTOK + l];
        s += v; s2 += v * v;
    }
#pragma unroll
    for (int o = 16; o; o >>= 1) {
        s  += __shfl_xor_sync(0xffffffffu, s, o);
        s2 += __shfl_xor_sync(0xffffffffu, s2, o);
    }
    __shared__ float rs[8], rs2[8];
    if ((threadIdx.x & 31) == 0) { rs[threadIdx.x >> 5] = s; rs2[threadIdx.x >> 5] = s2; }
    __syncthreads();
    if (threadIdx.x == 0) {
        float S = 0.f, S2 = 0.f;
#pragma unroll
        for (int i = 0; i < 8; i++) { S += rs[i]; S2 += rs2[i]; }
        const float inv_cnt = 1.f / (float)(NBAT * LTOK);
        const float mu = S * inv_cnt;
        const float var = S2 * inv_cnt - mu * mu;
        mean[c] = mu;
        rstd[c] = rsqrtf(var + EPSV);
    }
}

// ---------------- BN apply + residual ---------------------------------------
__global__ __launch_bounds__(256)
void bn_apply_kernel(const float* __restrict__ wy, const float* __restrict__ x,
                     const float* __restrict__ gamma, const float* __restrict__ beta,
                     const float* __restrict__ mean, const float* __restrict__ rstd,
                     float* __restrict__ out)
{
    const size_t i = (size_t)blockIdx.x * blockDim.x + threadIdx.x;
    const size_t base = i * 4;
    if (base >= (size_t)NBAT * CCH * LTOK) return;
    const int c = (int)((base >> 12) & (CCH - 1));
    const float4 w  = *(const float4*)(wy + base);
    const float4 xv = *(const float4*)(x + base);
    const float mu = mean[c];
    const float sc = rstd[c] * gamma[c];
    const float be = beta[c];
    float4 o;
    o.x = (w.x - mu) * sc + be + xv.x;
    o.y = (w.y - mu) * sc + be + xv.y;
    o.z = (w.z - mu) * sc + be + xv.z;
    o.w = (w.w - mu) * sc + be + xv.w;
    *(float4*)(out + base) = o;
}

// ---------------- launch ------------------------------------------------------
extern "C" void kernel_launch(void* const* d_in, const int* in_sizes, int n_in,
                              void* d_out, int out_size)
{
    const float* x     = (const float*)d_in[0];
    const float* g_w   = (const float*)d_in[1];
    const float* g_b   = (const float*)d_in[2];
    const float* th_w  = (const float*)d_in[3];
    const float* th_b  = (const float*)d_in[4];
    const float* ph_w  = (const float*)d_in[5];
    const float* ph_b  = (const float*)d_in[6];
    const float* wz_w  = (const float*)d_in[7];
    const float* wz_b  = (const float*)d_in[8];
    const float* gamma = (const float*)d_in[9];
    const float* beta  = (const float*)d_in[10];
    float* out = (float*)d_out;

    __nv_bfloat16 *p_thh, *p_thl, *p_phh, *p_phl, *p_gh, *p_gl;
    __nv_bfloat16 *p_ph, *p_pl, *p_y2h, *p_y2l, *p_wzh, *p_wzl;
    float *p_f, *p_wy, *p_mean, *p_rstd;
    cudaGetSymbolAddress((void**)&p_thh, d_thh);
    cudaGetSymbolAddress((void**)&p_thl, d_thl);
    cudaGetSymbolAddress((void**)&p_phh, d_phh);
    cudaGetSymbolAddress((void**)&p_phl, d_phl);
    cudaGetSymbolAddress((void**)&p_gh,  d_gh);
    cudaGetSymbolAddress((void**)&p_gl,  d_gl);
    cudaGetSymbolAddress((void**)&p_f,   d_f);
    cudaGetSymbolAddress((void**)&p_ph,  d_ph_);
    cudaGetSymbolAddress((void**)&p_pl,  d_pl_);
    cudaGetSymbolAddress((void**)&p_y2h, d_y2h);
    cudaGetSymbolAddress((void**)&p_y2l, d_y2l);
    cudaGetSymbolAddress((void**)&p_wzh, d_wzh);
    cudaGetSymbolAddress((void**)&p_wzl, d_wzl);
    cudaGetSymbolAddress((void**)&p_wy,  d_wy);
    cudaGetSymbolAddress((void**)&p_mean, d_mean);
    cudaGetSymbolAddress((void**)&p_rstd, d_rstd);

    cudaFuncSetAttribute(gemm_pre<0, false>, cudaFuncAttributeMaxDynamicSharedMemorySize, GSMEM);
    cudaFuncSetAttribute(gemm_pre<1, false>, cudaFuncAttributeMaxDynamicSharedMemorySize, GSMEM);
    cudaFuncSetAttribute(gemm_pre<0, true >, cudaFuncAttributeMaxDynamicSharedMemorySize, GSMEM);
    cudaFuncSetAttribute(proj_bf16x3<false, true, 2>, cudaFuncAttributeMaxDynamicSharedMemorySize, PSMEM);
    cudaFuncSetAttribute(proj_bf16x3<true, false, 1>, cudaFuncAttributeMaxDynamicSharedMemorySize, PSMEM);

    const dim3 b256(256), b512(512);
    const long long sX = (long long)CCH * LTOK;
    const long long sT = (long long)LTOK * CIN;   // thetaT/phiT/y2 stride
    const long long sG = (long long)CIN * LTOK;   // g stride
    const long long sF = (long long)LTOK * LTOK;  // f / P stride
    const long long sW = (long long)CCH * LTOK;   // wy stride

    // 0) split Wz
    wz_split_kernel<<<CCH * CIN / 512, b256>>>(wz_w, p_wzh, p_wzl);

    // 1) projections (tensor path) -> split bf16
    //    thetaT/phiT (L x CI): A = x (C,L) scatter (K x M), B = W (CI,C) direct, col bias
    {
        dim3 g(CIN / 128, LTOK / 128, NBAT);
        proj_bf16x3<false, true, 2><<<g, b256, PSMEM>>>(
            x, LTOK, sX, th_w, CCH, 0, p_thh, p_thl, CIN, sT, th_b, CCH);
        proj_bf16x3<false, true, 2><<<g, b256, PSMEM>>>(
            x, LTOK, sX, ph_w, CCH, 0, p_phh, p_phl, CIN, sT, ph_b, CCH);
    }
    //    g (CI x L): A = W (CI,C) direct, B = x (C,L) scatter (K x N), row bias
    {
        dim3 g(LTOK / 128, CIN / 128, NBAT);
        proj_bf16x3<true, false, 1><<<g, b256, PSMEM>>>(
            g_w, CCH, 0, x, LTOK, sX, p_gh, p_gl, LTOK, sG, g_b, CCH);
    }
    // 2) f = thetaT · phiT^T  (M=N=4096, K=256)
    {
        dim3 g(LTOK / 256, LTOK / 128, NBAT);
        gemm_pre<0, false><<<g, b512, GSMEM>>>(p_thh, p_thl, CIN, sT,
                                               p_phh, p_phl, CIN, sT,
                                               p_f, nullptr, nullptr, LTOK, sF,
                                               nullptr, CIN);
    }
    // 3) softmax -> P hi/lo
    softmax_kernel<<<NBAT * LTOK, b256>>>(p_f, p_ph, p_pl);
    // 4) y2 (L x CI) = P · g^T  (M=4096, N=256, K=4096) -> split bf16
    {
        dim3 g(CIN / 256, LTOK / 128, NBAT);
        gemm_pre<1, false><<<g, b512, GSMEM>>>(p_ph, p_pl, LTOK, sF,
                                               p_gh, p_gl, LTOK, sG,
                                               nullptr, p_y2h, p_y2l, CIN, sT,
                                               nullptr, LTOK);
    }
    // 5) w_y (C x L) = Wz · y2^T (M=512, N=4096, K=256) + bias
    {
        dim3 g(LTOK / 256, CCH / 128, NBAT);
        gemm_pre<0, true><<<g, b512, GSMEM>>>(p_wzh, p_wzl, CIN, 0,
                                              p_y2h, p_y2l, CIN, sT,
                                              p_wy, nullptr, nullptr, LTOK, sW,
                                              wz_b, CIN);
    }
    // 6) BN stats
    bn_stats_kernel<<<CCH, b256>>>(p_wy, p_mean, p_rstd);
    // 7) BN apply + residual
    {
        const size_t total4 = (size_t)NBAT * CCH * LTOK / 4;
        bn_apply_kernel<<<(unsigned)((total4 + 255) / 256), b256>>>(
            p_wy, x, gamma, beta, p_mean, p_rstd, out);
    }
}

// round 7
// speedup vs baseline: 1.4981x; 1.4981x over previous
#include <cuda_runtime.h>
#include <cuda_bf16.h>
#include <cstdint>
#include <cstddef>

#define LTOK 4096   // H*W tokens
#define CCH  512    // in channels
#define CIN  256    // inter channels
#define NBAT 4      // batch
#define EPSV 1e-5f

// ---------------- scratch (device globals: no runtime allocation) ----------
__device__ __nv_bfloat16 d_xth[(size_t)NBAT * LTOK * CCH];  // x^T hi (L,C)
__device__ __nv_bfloat16 d_xtl[(size_t)NBAT * LTOK * CCH];  // x^T lo
__device__ __nv_bfloat16 d_thwh[CIN * CCH], d_thwl[CIN * CCH];
__device__ __nv_bfloat16 d_phwh[CIN * CCH], d_phwl[CIN * CCH];
__device__ __nv_bfloat16 d_gwh [CIN * CCH], d_gwl [CIN * CCH];
__device__ __nv_bfloat16 d_wzh [CCH * CIN], d_wzl [CCH * CIN];
__device__ __nv_bfloat16 d_thh[(size_t)NBAT * LTOK * CIN];  // theta^T hi (L,CI)
__device__ __nv_bfloat16 d_thl[(size_t)NBAT * LTOK * CIN];
__device__ __nv_bfloat16 d_phh[(size_t)NBAT * LTOK * CIN];  // phi^T hi
__device__ __nv_bfloat16 d_phl[(size_t)NBAT * LTOK * CIN];
__device__ __nv_bfloat16 d_gh [(size_t)NBAT * CIN * LTOK];  // g hi (CI,L)
__device__ __nv_bfloat16 d_gl [(size_t)NBAT * CIN * LTOK];
__device__ float         d_f  [(size_t)NBAT * LTOK * LTOK]; // 268 MB logits
__device__ __nv_bfloat16 d_ph_[(size_t)NBAT * LTOK * LTOK]; // softmax P hi
__device__ __nv_bfloat16 d_pl_[(size_t)NBAT * LTOK * LTOK]; // softmax P lo
__device__ __nv_bfloat16 d_y2h[(size_t)NBAT * LTOK * CIN];  // y2 hi (L,CI)
__device__ __nv_bfloat16 d_y2l[(size_t)NBAT * LTOK * CIN];
__device__ float d_wy[(size_t)NBAT * CCH * LTOK];
__device__ float d_mean[CCH];
__device__ float d_rstd[CCH];

// =========================== helpers ========================================
__device__ __forceinline__ uint32_t smem_u32(const void* p) {
    uint32_t a;
    asm("{ .reg .u64 t; cvta.to.shared.u64 t, %1; cvt.u32.u64 %0, t; }" : "=r"(a) : "l"(p));
    return a;
}
__device__ __forceinline__ uint32_t cvt2bf(float x, float y) {
    uint32_t r;
    asm("cvt.rn.bf16x2.f32 %0, %1, %2;" : "=r"(r) : "f"(y), "f"(x));
    return r;
}
__device__ __forceinline__ void split2(float x, float y, uint32_t& h, uint32_t& l) {
    h = cvt2bf(x, y);
    const float hx = __uint_as_float(h << 16);
    const float hy = __uint_as_float(h & 0xffff0000u);
    l = cvt2bf(x - hx, y - hy);
}
__device__ __forceinline__ void mma16816(float c[4], const uint32_t a[4],
                                         uint32_t b0, uint32_t b1) {
    asm volatile(
        "mma.sync.aligned.m16n8k16.row.col.f32.bf16.bf16.f32 "
        "{%0,%1,%2,%3}, {%4,%5,%6,%7}, {%8,%9}, {%0,%1,%2,%3};"
        : "+f"(c[0]), "+f"(c[1]), "+f"(c[2]), "+f"(c[3])
        : "r"(a[0]), "r"(a[1]), "r"(a[2]), "r"(a[3]), "r"(b0), "r"(b1));
}
__device__ __forceinline__ void cp16(uint32_t dst, const void* src) {
    asm volatile("cp.async.cg.shared.global [%0], [%1], 16;" :: "r"(dst), "l"(src) : "memory");
}
#define CP_COMMIT() asm volatile("cp.async.commit_group;" ::: "memory")
#define CP_WAIT1()  asm volatile("cp.async.wait_group 1;" ::: "memory")

// =========== unified GEMM: bf16 hi/lo pre-split inputs, cp.async pipeline ===
// D(MxN) = (Ah+Al)(MxK) · (Bh+Bl)(NxK)^T via 3 MMA terms. Row-major K-contig.
// CTA tile 128(M) x 256(N), K-step 64, 512 threads, 2 stages.
// OUTM 0: fp32 D; 1: bf16 Dh/Dl.  BMODE 0: none, 1: per-M-row, 2: per-N-col.
constexpr int SA_U = 128 * 36;
constexpr int SB_U = 256 * 36;
constexpr int STAGE_U = 2 * SA_U + 2 * SB_U;
constexpr int G_AH = 0, G_AL = SA_U, G_BH = 2 * SA_U, G_BL = 2 * SA_U + SB_U;
constexpr int GSMEM = 2 * STAGE_U * 4;          // 221184 B

template<int OUTM, int BMODE>
__global__ void __launch_bounds__(512, 1)
gemm_pre(const __nv_bfloat16* __restrict__ Ah, const __nv_bfloat16* __restrict__ Al,
         int lda, long long sA,
         const __nv_bfloat16* __restrict__ Bh, const __nv_bfloat16* __restrict__ Bl,
         int ldb, long long sB,
         float* __restrict__ D, __nv_bfloat16* __restrict__ Dh,
         __nv_bfloat16* __restrict__ Dl, int ldc, long long sD,
         const float* __restrict__ bias, int K)
{
    extern __shared__ uint32_t sm[];
    const uint32_t sbase = smem_u32(sm);
    Ah += (size_t)blockIdx.z * sA;  Al += (size_t)blockIdx.z * sA;
    Bh += (size_t)blockIdx.z * sB;  Bl += (size_t)blockIdx.z * sB;
    if (OUTM == 0) D += (size_t)blockIdx.z * sD;
    else { Dh += (size_t)blockIdx.z * sD; Dl += (size_t)blockIdx.z * sD; }

    const int bm = blockIdx.y * 128;
    const int bn = blockIdx.x * 256;
    const int tid  = threadIdx.x;
    const int lane = tid & 31;
    const int wid  = tid >> 5;
    const int wm = (wid & 3) * 32;    // 4 warps in M
    const int wn = (wid >> 2) * 64;   // 4 warps in N

    float acc[2][8][4];
#pragma unroll
    for (int a = 0; a < 2; a++)
#pragma unroll
        for (int b = 0; b < 8; b++)
#pragma unroll
            for (int c = 0; c < 4; c++) acc[a][b][c] = 0.f;

    const int KT = K / 64;

    auto issue = [&](int kt) {
        if (kt >= KT) return;
        const uint32_t sb = sbase + (uint32_t)(kt & 1) * (STAGE_U * 4);
        const int k0 = kt * 64;
#pragma unroll
        for (int p = 0; p < 2; p++) {
            const int c = tid + p * 512;
            const int r = c >> 3, cc = c & 7;
            const uint32_t d = sb + (uint32_t)((r * 36 + cc * 4) << 2);
            const size_t go = (size_t)(bm + r) * lda + k0 + cc * 8;
            cp16(d + G_AH * 4, Ah + go);
            cp16(d + G_AL * 4, Al + go);
        }
#pragma unroll
        for (int p = 0; p < 4; p++) {
            const int c = tid + p * 512;
            const int r = c >> 3, cc = c & 7;
            const uint32_t d = sb + (uint32_t)((r * 36 + cc * 4) << 2);
            const size_t go = (size_t)(bn + r) * ldb + k0 + cc * 8;
            cp16(d + G_BH * 4, Bh + go);
            cp16(d + G_BL * 4, Bl + go);
        }
    };

    issue(0); CP_COMMIT();
    issue(1); CP_COMMIT();

    const int arow = wm + (lane >> 2);
    const int brow = wn + (lane >> 2);
    const int kl = lane & 3;

    for (int kt = 0; kt < KT; kt++) {
        CP_WAIT1();
        __syncthreads();
        const uint32_t* s = sm + (kt & 1) * STAGE_U;
#pragma unroll
        for (int ss = 0; ss < 4; ss++) {
            const int kq = ss * 8 + kl;
            uint32_t Ahf[2][4], Alf[2][4];
#pragma unroll
            for (int mt = 0; mt < 2; mt++) {
                const int b0 = (arow + mt * 16) * 36 + kq;
                Ahf[mt][0] = s[G_AH + b0];       Ahf[mt][1] = s[G_AH + b0 + 288];
                Ahf[mt][2] = s[G_AH + b0 + 4];   Ahf[mt][3] = s[G_AH + b0 + 292];
                Alf[mt][0] = s[G_AL + b0];       Alf[mt][1] = s[G_AL + b0 + 288];
                Alf[mt][2] = s[G_AL + b0 + 4];   Alf[mt][3] = s[G_AL + b0 + 292];
            }
#pragma unroll
            for (int nt = 0; nt < 8; nt++) {
                const int c0 = (brow + nt * 8) * 36 + kq;
                const uint32_t b0h = s[G_BH + c0], b1h = s[G_BH + c0 + 4];
                const uint32_t b0l = s[G_BL + c0], b1l = s[G_BL + c0 + 4];
#pragma unroll
                for (int mt = 0; mt < 2; mt++) {
                    mma16816(acc[mt][nt], Ahf[mt], b0h, b1h);  // hi*hi
                    mma16816(acc[mt][nt], Ahf[mt], b0l, b1l);  // hi*lo
                    mma16816(acc[mt][nt], Alf[mt], b0h, b1h);  // lo*hi
                }
            }
        }
        __syncthreads();
        issue(kt + 2); CP_COMMIT();
    }

    // ---- epilogue ----
#pragma unroll
    for (int mt = 0; mt < 2; mt++) {
        const int r0 = bm + wm + mt * 16 + (lane >> 2);
        const float bv0 = (BMODE == 1) ? bias[r0]     : 0.f;
        const float bv8 = (BMODE == 1) ? bias[r0 + 8] : 0.f;
#pragma unroll
        for (int nt = 0; nt < 8; nt++) {
            const int c0 = bn + wn + nt * 8 + (lane & 3) * 2;
            float cb0 = 0.f, cb1 = 0.f;
            if (BMODE == 2) { const float2 bb = *(const float2*)&bias[c0]; cb0 = bb.x; cb1 = bb.y; }
            const float o00 = acc[mt][nt][0] + bv0 + cb0;
            const float o01 = acc[mt][nt][1] + bv0 + cb1;
            const float o10 = acc[mt][nt][2] + bv8 + cb0;
            const float o11 = acc[mt][nt][3] + bv8 + cb1;
            if (OUTM == 0) {
                *(float2*)&D[(size_t)r0 * ldc + c0]       = make_float2(o00, o01);
                *(float2*)&D[(size_t)(r0 + 8) * ldc + c0] = make_float2(o10, o11);
            } else {
                uint32_t h, l;
                split2(o00, o01, h, l);
                *(uint32_t*)(Dh + (size_t)r0 * ldc + c0) = h;
                *(uint32_t*)(Dl + (size_t)r0 * ldc + c0) = l;
                split2(o10, o11, h, l);
                *(uint32_t*)(Dh + (size_t)(r0 + 8) * ldc + c0) = h;
                *(uint32_t*)(Dl + (size_t)(r0 + 8) * ldc + c0) = l;
            }
        }
    }
}

// ---------------- generic fp32 -> bf16 hi/lo split (weights) ----------------
__global__ __launch_bounds__(256)
void split_kernel(const float* __restrict__ w,
                  __nv_bfloat16* __restrict__ wh, __nv_bfloat16* __restrict__ wl)
{
    const int p = blockIdx.x * 256 + threadIdx.x;   // pair index
    const float2 v = *(const float2*)&w[2 * p];
    uint32_t h, l;
    split2(v.x, v.y, h, l);
    ((uint32_t*)wh)[p] = h;
    ((uint32_t*)wl)[p] = l;
}

// ---------------- x (C,L) -> x^T hi/lo (L,C) transpose + split --------------
__global__ __launch_bounds__(256)
void xsplitT_kernel(const float* __restrict__ x,
                    __nv_bfloat16* __restrict__ xh, __nv_bfloat16* __restrict__ xl)
{
    __shared__ float t[32][33];
    const float* xb = x + (size_t)blockIdx.z * CCH * LTOK;
    const int lbase = blockIdx.x * 32;
    const int cbase = blockIdx.y * 32;
    const int tid = threadIdx.x;

    const int col = tid & 31, r0 = tid >> 5;   // 8 c-rows per pass
#pragma unroll
    for (int i = 0; i < 4; i++) {
        const int r = r0 + i * 8;
        t[r][col] = xb[(size_t)(cbase + r) * LTOK + lbase + col];
    }
    __syncthreads();

    const int cpair = (tid & 15) * 2;
    const int l0 = tid >> 4;                    // 16 l-rows per pass
    const size_t obase = (size_t)blockIdx.z * LTOK * CCH;
#pragma unroll
    for (int i = 0; i < 2; i++) {
        const int l = l0 + i * 16;
        uint32_t h, lo;
        split2(t[cpair][l], t[cpair + 1][l], h, lo);
        const size_t o = (obase + (size_t)(lbase + l) * CCH + cbase + cpair) >> 1;
        ((uint32_t*)xh)[o] = h;
        ((uint32_t*)xl)[o] = lo;
    }
}

// ---------------- row softmax over f -> P hi/lo bf16 -------------------------
__global__ __launch_bounds__(256)
void softmax_kernel(const float* __restrict__ f,
                    __nv_bfloat16* __restrict__ ph, __nv_bfloat16* __restrict__ pl)
{
    const size_t rbase = (size_t)blockIdx.x * LTOK;
    const float* row = f + rbase;
    const int tid = threadIdx.x;

    float4 v[4];
    float m = -1e30f;
#pragma unroll
    for (int i = 0; i < 4; i++) {
        v[i] = *(const float4*)&row[tid * 4 + i * 1024];
        m = fmaxf(m, fmaxf(fmaxf(v[i].x, v[i].y), fmaxf(v[i].z, v[i].w)));
    }
#pragma unroll
    for (int o = 16; o; o >>= 1) m = fmaxf(m, __shfl_xor_sync(0xffffffffu, m, o));

    __shared__ float red[8];
    if ((tid & 31) == 0) red[tid >> 5] = m;
    __syncthreads();
    float gmax = -1e30f;
#pragma unroll
    for (int i = 0; i < 8; i++) gmax = fmaxf(gmax, red[i]);

    float s = 0.f;
#pragma unroll
    for (int i = 0; i < 4; i++) {
        v[i].x = __expf(v[i].x - gmax);
        v[i].y = __expf(v[i].y - gmax);
        v[i].z = __expf(v[i].z - gmax);
        v[i].w = __expf(v[i].w - gmax);
        s += v[i].x + v[i].y + v[i].z + v[i].w;
    }
#pragma unroll
    for (int o = 16; o; o >>= 1) s += __shfl_xor_sync(0xffffffffu, s, o);
    __syncthreads();
    if ((tid & 31) == 0) red[tid >> 5] = s;
    __syncthreads();
    float gsum = 0.f;
#pragma unroll
    for (int i = 0; i < 8; i++) gsum += red[i];
    const float inv = 1.f / gsum;

#pragma unroll
    for (int i = 0; i < 4; i++) {
        const float p0 = v[i].x * inv, p1 = v[i].y * inv;
        const float p2 = v[i].z * inv, p3 = v[i].w * inv;
        uint2 H, L;
        split2(p0, p1, H.x, L.x);
        split2(p2, p3, H.y, L.y);
        const size_t off = rbase + tid * 4 + i * 1024;
        *(uint2*)(ph + off) = H;
        *(uint2*)(pl + off) = L;
    }
}

// ---------------- batchnorm statistics ---------------------------------------
__global__ __launch_bounds__(256)
void bn_stats_kernel(const float* __restrict__ wy,
                     float* __restrict__ mean, float* __restrict__ rstd)
{
    const int c = blockIdx.x;
    float s = 0.f, s2 = 0.f;
    for (int idx = threadIdx.x; idx < NBAT * LTOK; idx += 256) {
        const int n = idx >> 12;
        const int l = idx & (LTOK - 1);
        const float v = wy[((size_t)n * CCH + c) * LTOK + l];
        s += v; s2 += v * v;
    }
#pragma unroll
    for (int o = 16; o; o >>= 1) {
        s  += __shfl_xor_sync(0xffffffffu, s, o);
        s2 += __shfl_xor_sync(0xffffffffu, s2, o);
    }
    __shared__ float rs[8], rs2[8];
    if ((threadIdx.x & 31) == 0) { rs[threadIdx.x >> 5] = s; rs2[threadIdx.x >> 5] = s2; }
    __syncthreads();
    if (threadIdx.x == 0) {
        float S = 0.f, S2 = 0.f;
#pragma unroll
        for (int i = 0; i < 8; i++) { S += rs[i]; S2 += rs2[i]; }
        const float inv_cnt = 1.f / (float)(NBAT * LTOK);
        const float mu = S * inv_cnt;
        const float var = S2 * inv_cnt - mu * mu;
        mean[c] = mu;
        rstd[c] = rsqrtf(var + EPSV);
    }
}

// ---------------- BN apply + residual ---------------------------------------
__global__ __launch_bounds__(256)
void bn_apply_kernel(const float* __restrict__ wy, const float* __restrict__ x,
                     const float* __restrict__ gamma, const float* __restrict__ beta,
                     const float* __restrict__ mean, const float* __restrict__ rstd,
                     float* __restrict__ out)
{
    const size_t i = (size_t)blockIdx.x * blockDim.x + threadIdx.x;
    const size_t base = i * 4;
    if (base >= (size_t)NBAT * CCH * LTOK) return;
    const int c = (int)((base >> 12) & (CCH - 1));
    const float4 w  = *(const float4*)(wy + base);
    const float4 xv = *(const float4*)(x + base);
    const float mu = mean[c];
    const float sc = rstd[c] * gamma[c];
    const float be = beta[c];
    float4 o;
    o.x = (w.x - mu) * sc + be + xv.x;
    o.y = (w.y - mu) * sc + be + xv.y;
    o.z = (w.z - mu) * sc + be + xv.z;
    o.w = (w.w - mu) * sc + be + xv.w;
    *(float4*)(out + base) = o;
}

// ---------------- launch ------------------------------------------------------
extern "C" void kernel_launch(void* const* d_in, const int* in_sizes, int n_in,
                              void* d_out, int out_size)
{
    const float* x     = (const float*)d_in[0];
    const float* g_w   = (const float*)d_in[1];
    const float* g_b   = (const float*)d_in[2];
    const float* th_w  = (const float*)d_in[3];
    const float* th_b  = (const float*)d_in[4];
    const float* ph_w  = (const float*)d_in[5];
    const float* ph_b  = (const float*)d_in[6];
    const float* wz_w  = (const float*)d_in[7];
    const float* wz_b  = (const float*)d_in[8];
    const float* gamma = (const float*)d_in[9];
    const float* beta  = (const float*)d_in[10];
    float* out = (float*)d_out;

    __nv_bfloat16 *p_xth, *p_xtl, *p_thwh, *p_thwl, *p_phwh, *p_phwl;
    __nv_bfloat16 *p_gwh, *p_gwl, *p_wzh, *p_wzl;
    __nv_bfloat16 *p_thh, *p_thl, *p_phh, *p_phl, *p_gh, *p_gl;
    __nv_bfloat16 *p_ph, *p_pl, *p_y2h, *p_y2l;
    float *p_f, *p_wy, *p_mean, *p_rstd;
    cudaGetSymbolAddress((void**)&p_xth,  d_xth);
    cudaGetSymbolAddress((void**)&p_xtl,  d_xtl);
    cudaGetSymbolAddress((void**)&p_thwh, d_thwh);
    cudaGetSymbolAddress((void**)&p_thwl, d_thwl);
    cudaGetSymbolAddress((void**)&p_phwh, d_phwh);
    cudaGetSymbolAddress((void**)&p_phwl, d_phwl);
    cudaGetSymbolAddress((void**)&p_gwh,  d_gwh);
    cudaGetSymbolAddress((void**)&p_gwl,  d_gwl);
    cudaGetSymbolAddress((void**)&p_wzh,  d_wzh);
    cudaGetSymbolAddress((void**)&p_wzl,  d_wzl);
    cudaGetSymbolAddress((void**)&p_thh,  d_thh);
    cudaGetSymbolAddress((void**)&p_thl,  d_thl);
    cudaGetSymbolAddress((void**)&p_phh,  d_phh);
    cudaGetSymbolAddress((void**)&p_phl,  d_phl);
    cudaGetSymbolAddress((void**)&p_gh,   d_gh);
    cudaGetSymbolAddress((void**)&p_gl,   d_gl);
    cudaGetSymbolAddress((void**)&p_f,    d_f);
    cudaGetSymbolAddress((void**)&p_ph,   d_ph_);
    cudaGetSymbolAddress((void**)&p_pl,   d_pl_);
    cudaGetSymbolAddress((void**)&p_y2h,  d_y2h);
    cudaGetSymbolAddress((void**)&p_y2l,  d_y2l);
    cudaGetSymbolAddress((void**)&p_wy,   d_wy);
    cudaGetSymbolAddress((void**)&p_mean, d_mean);
    cudaGetSymbolAddress((void**)&p_rstd, d_rstd);

    cudaFuncSetAttribute(gemm_pre<1, 2>, cudaFuncAttributeMaxDynamicSharedMemorySize, GSMEM);
    cudaFuncSetAttribute(gemm_pre<1, 1>, cudaFuncAttributeMaxDynamicSharedMemorySize, GSMEM);
    cudaFuncSetAttribute(gemm_pre<0, 0>, cudaFuncAttributeMaxDynamicSharedMemorySize, GSMEM);
    cudaFuncSetAttribute(gemm_pre<1, 0>, cudaFuncAttributeMaxDynamicSharedMemorySize, GSMEM);
    cudaFuncSetAttribute(gemm_pre<0, 1>, cudaFuncAttributeMaxDynamicSharedMemorySize, GSMEM);

    const dim3 b256(256), b512(512);
    const long long sXT = (long long)LTOK * CCH;  // xT stride
    const long long sT  = (long long)LTOK * CIN;  // thetaT/phiT/y2 stride
    const long long sG  = (long long)CIN * LTOK;  // g stride
    const long long sF  = (long long)LTOK * LTOK; // f / P stride
    const long long sW  = (long long)CCH * LTOK;  // wy stride

    // 0) split all weights + transpose-split x
    split_kernel<<<CIN * CCH / 512, b256>>>(th_w, p_thwh, p_thwl);
    split_kernel<<<CIN * CCH / 512, b256>>>(ph_w, p_phwh, p_phwl);
    split_kernel<<<CIN * CCH / 512, b256>>>(g_w,  p_gwh,  p_gwl);
    split_kernel<<<CCH * CIN / 512, b256>>>(wz_w, p_wzh,  p_wzl);
    {
        dim3 g(LTOK / 32, CCH / 32, NBAT);
        xsplitT_kernel<<<g, b256>>>(x, p_xth, p_xtl);
    }

    // 1) projections — all gemm_pre
    //    thetaT/phiT (L x CI) = xT(L x C) · W(CI x C)^T + b[col]
    {
        dim3 g(CIN / 256, LTOK / 128, NBAT);
        gemm_pre<1, 2><<<g, b512, GSMEM>>>(p_xth, p_xtl, CCH, sXT,
                                           p_thwh, p_thwl, CCH, 0,
                                           nullptr, p_thh, p_thl, CIN, sT,
                                           th_b, CCH);
        gemm_pre<1, 2><<<g, b512, GSMEM>>>(p_xth, p_xtl, CCH, sXT,
                                           p_phwh, p_phwl, CCH, 0,
                                           nullptr, p_phh, p_phl, CIN, sT,
                                           ph_b, CCH);
    }
    //    g (CI x L) = W(CI x C) · xT(L x C)^T + b[row]
    {
        dim3 g(LTOK / 256, CIN / 128, NBAT);
        gemm_pre<1, 1><<<g, b512, GSMEM>>>(p_gwh, p_gwl, CCH, 0,
                                           p_xth, p_xtl, CCH, sXT,
                                           nullptr, p_gh, p_gl, LTOK, sG,
                                           g_b, CCH);
    }
    // 2) f = thetaT · phiT^T  (M=N=4096, K=256)
    {
        dim3 g(LTOK / 256, LTOK / 128, NBAT);
        gemm_pre<0, 0><<<g, b512, GSMEM>>>(p_thh, p_thl, CIN, sT,
                                           p_phh, p_phl, CIN, sT,
                                           p_f, nullptr, nullptr, LTOK, sF,
                                           nullptr, CIN);
    }
    // 3) softmax -> P hi/lo
    softmax_kernel<<<NBAT * LTOK, b256>>>(p_f, p_ph, p_pl);
    // 4) y2 (L x CI) = P · g^T  (M=4096, N=256, K=4096) -> split bf16
    {
        dim3 g(CIN / 256, LTOK / 128, NBAT);
        gemm_pre<1, 0><<<g, b512, GSMEM>>>(p_ph, p_pl, LTOK, sF,
                                           p_gh, p_gl, LTOK, sG,
                                           nullptr, p_y2h, p_y2l, CIN, sT,
                                           nullptr, LTOK);
    }
    // 5) w_y (C x L) = Wz · y2^T (M=512, N=4096, K=256) + bias
    {
        dim3 g(LTOK / 256, CCH / 128, NBAT);
        gemm_pre<0, 1><<<g, b512, GSMEM>>>(p_wzh, p_wzl, CIN, 0,
                                           p_y2h, p_y2l, CIN, sT,
                                           p_wy, nullptr, nullptr, LTOK, sW,
                                           wz_b, CIN);
    }
    // 6) BN stats
    bn_stats_kernel<<<CCH, b256>>>(p_wy, p_mean, p_rstd);
    // 7) BN apply + residual
    {
        const size_t total4 = (size_t)NBAT * CCH * LTOK / 4;
        bn_apply_kernel<<<(unsigned)((total4 + 255) / 256), b256>>>(
            p_wy, x, gamma, beta, p_mean, p_rstd, out);
    }
}